// round 15
// baseline (speedup 1.0000x reference)
#include <cuda_runtime.h>

#define Bb 4
#define Cc 64
#define Nn 8192
#define Kk 16
#define Dd 64
#define S_CHUNK 4
#define CHUNK_N (Nn / S_CHUNK)
#define TILE_C 512
#define TPAIR (TILE_C / 2)

typedef unsigned long long ull;

// ---------------- scratch (static __device__, no allocations) ----------------
__device__ __align__(16) float g_xT[Bb * Nn * Cc];       // x transposed: (B, N, C)
__device__ float g_sq[Bb * Nn];                          // squared norms of pos
__device__ int   g_idx[Bb * Nn * Kk];                    // knn indices
__device__ __align__(16) ull g_pk[(size_t)Bb * Nn * S_CHUNK * 16]; // partial sorted keys
__device__ __align__(16) float g_WsumNeg[Cc * Dd];       // -sum_k W[k,c,d]
__device__ float g_partial[(Bb * Nn / 64) * 2 * Dd];     // per-block BN partials (sum, sumsq)
__device__ float g_scale[Dd], g_shift[Dd];

// ---------------- f32x2 helpers ---------------------------------------------
#define FMA2(d, a, b) asm("fma.rn.f32x2 %0, %1, %2, %0;" : "+l"(d) : "l"(a), "l"(b))
__device__ __forceinline__ ull mul2(ull a, ull b) {
    ull r; asm("mul.rn.f32x2 %0, %1, %2;" : "=l"(r) : "l"(a), "l"(b)); return r;
}
__device__ __forceinline__ ull fma2(ull a, ull b, ull c) {
    ull r; asm("fma.rn.f32x2 %0, %1, %2, %3;" : "=l"(r) : "l"(a), "l"(b), "l"(c)); return r;
}
__device__ __forceinline__ ull add2(ull a, ull b) {
    ull r; asm("add.rn.f32x2 %0, %1, %2;" : "=l"(r) : "l"(a), "l"(b)); return r;
}
__device__ __forceinline__ ull pack2(float x) {
    ull r; asm("mov.b64 %0, {%1, %1};" : "=l"(r) : "r"(__float_as_uint(x))); return r;
}
__device__ __forceinline__ ull pack2f(float a, float b) {
    ull r; asm("mov.b64 %0, {%1, %2};" : "=l"(r) : "r"(__float_as_uint(a)), "r"(__float_as_uint(b))); return r;
}
__device__ __forceinline__ void unpack2(ull v, float& lo, float& hi) {
    unsigned a, b;
    asm("mov.b64 {%0, %1}, %2;" : "=r"(a), "=r"(b) : "l"(v));
    lo = __uint_as_float(a); hi = __uint_as_float(b);
}

// ---------------- prep: squared norms of pos --------------------------------
// Match XLA reduce lowering exactly: ((x*x + y*y) + z*z), no fma contraction.
__global__ void prep_sq(const float* __restrict__ pos) {
    int b = blockIdx.y;
    int n = blockIdx.x * 256 + threadIdx.x;
    const float* pb = pos + b * 3 * Nn;
    float x = pb[n], y = pb[Nn + n], z = pb[2 * Nn + n];
    float s = __fadd_rn(__fadd_rn(__fmul_rn(x, x), __fmul_rn(y, y)), __fmul_rn(z, z));
    g_sq[b * Nn + n] = s;
}

// ---------------- prep: transpose x (B,C,N) -> xT (B,N,C) -------------------
__global__ void prep_xT(const float* __restrict__ x) {
    __shared__ float t[32][33];
    int b = blockIdx.z;
    int n0 = blockIdx.x * 32, c0 = blockIdx.y * 32;
    int tx = threadIdx.x, ty = threadIdx.y;
#pragma unroll
    for (int i = 0; i < 4; ++i)
        t[ty + 8 * i][tx] = x[(size_t)b * Cc * Nn + (size_t)(c0 + ty + 8 * i) * Nn + n0 + tx];
    __syncthreads();
#pragma unroll
    for (int i = 0; i < 4; ++i)
        g_xT[(size_t)b * Nn * Cc + (size_t)(n0 + ty + 8 * i) * Cc + c0 + tx] = t[tx][ty + 8 * i];
}

// ---------------- prep: negated filter k-sum --------------------------------
__global__ void prep_wsum(const float* __restrict__ filt) {
    int i = blockIdx.x * 256 + threadIdx.x;  // 0..4095 = c*64+d
    float s = 0.f;
#pragma unroll
    for (int k = 0; k < Kk; ++k) s += filt[k * Cc * Dd + i];
    g_WsumNeg[i] = -s;
}

// ---------------- KNN keys ---------------------------------------------------
// Transformed key: (sortable(dn) << 32) | ~idx -> total order == top_k
// (value desc, idx asc). Keys are UNIQUE, so selection is a pure multiset
// top-16: any order-insensitive exact top-16 structure is bit-identical.
// Appends store RAW (d_bits<<32)|~idx; the sortable transform is applied in
// flush_merge (16 items per flush instead of per candidate).
__device__ __forceinline__ float key_val(ull k) {
    unsigned u = (unsigned)(k >> 32);
    unsigned tb = (u & 0x80000000u) ? (u ^ 0x80000000u) : ~u;
    return __int_as_float((int)tb);
}

// Branch-free predicated append: no BSSY/BSYNC region.
__device__ __forceinline__ void append1(unsigned sbase, int& cnt, float d, float vminf, unsigned nj) {
    unsigned hi = __float_as_uint(d);
    unsigned addr = sbase + (unsigned)cnt * 1024u;
    asm volatile(
        "{ .reg .pred p; .reg .b64 v;\n\t"
        "setp.ge.f32 p, %0, %1;\n\t"
        "mov.b64 v, {%3, %4};\n\t"
        "@p st.shared.b64 [%2], v; }"
        :: "f"(d), "f"(vminf), "r"(addr), "r"(nj), "r"(hi));
    cnt += (d >= vminf);
}

// Merge two descending sorted 16-lists -> top-16 descending (pair-max + bitonic).
__device__ __forceinline__ void merge16(ull (&kl)[16], const ull (&other)[16]) {
    ull m[16];
#pragma unroll
    for (int i = 0; i < 16; ++i) { ull a = kl[i], c = other[15 - i]; m[i] = a > c ? a : c; }
#pragma unroll
    for (int j = 8; j > 0; j >>= 1) {
#pragma unroll
        for (int i = 0; i < 16; ++i) {
            int l = i ^ j;
            if (l > i) {
                ull a = m[i], c = m[l];
                bool sw = a < c;
                m[i] = sw ? c : a;
                m[l] = sw ? a : c;
            }
        }
    }
#pragma unroll
    for (int i = 0; i < 16; ++i) kl[i] = m[i];
}

// Batched exact top-16 update: transform raw entries to sortable keys,
// bitonic-sort the buffer (desc), then merge16. kl stays sorted descending.
__device__ __forceinline__ void flush_merge(ull (&kl)[16], const ull* col, int cnt) {
    ull buf[16];
#pragma unroll
    for (int m = 0; m < 16; ++m) {
        ull raw = (m < cnt) ? col[m * 128] : 0ull;
        int bi = (int)(unsigned)(raw >> 32);
        unsigned u = (unsigned)(bi ^ ((bi >> 31) | 0x80000000));
        buf[m] = (m < cnt) ? (((ull)u << 32) | (unsigned)raw) : 0ull;
    }
    // bitonic sort, descending
#pragma unroll
    for (int k = 2; k <= 16; k <<= 1) {
#pragma unroll
        for (int j = k >> 1; j > 0; j >>= 1) {
#pragma unroll
            for (int i = 0; i < 16; ++i) {
                int l = i ^ j;
                if (l > i) {
                    bool desc = ((i & k) == 0);
                    ull a = buf[i], c = buf[l];
                    bool sw = desc ? (a < c) : (a > c);
                    buf[i] = sw ? c : a;
                    buf[l] = sw ? a : c;
                }
            }
        }
    }
    merge16(kl, buf);
}

// ---------------- KNN partial: top-16 within a 2048-candidate chunk ---------
// 512-candidate tiles (8KB) -> 24KB smem/block; launch_bounds forces 6
// blocks/SM (regs <= 85). Packed f32x2 arithmetic; per-lane rounding identical
// to scalar chain (2*inner exact => fma(2,t,-qs) == add(mul(2,t),-qs)).
__global__ void __launch_bounds__(128, 6) knn_partial(const float* __restrict__ pos) {
    __shared__ __align__(16) ull tx2[TPAIR], ty2[TPAIR], tz2[TPAIR], tns2[TPAIR];
    __shared__ ull sbuf[16][128];
    int b = blockIdx.z;
    int chunk = blockIdx.y;
    int tid = threadIdx.x;
    int n = blockIdx.x * 128 + tid;
    const float* pb = pos + b * 3 * Nn;
    float qxs = pb[n], qys = pb[Nn + n], qzs = pb[2 * Nn + n];
    float qss = g_sq[b * Nn + n];
    ull qx2 = pack2(qxs), qy2 = pack2(qys), qz2 = pack2(qzs);
    ull nqs2 = pack2(-qss), two2 = pack2(2.0f);

    // sentinel keys: descending, distinct; kl[15] decodes below any real key
    ull kl[16];
#pragma unroll
    for (int t = 0; t < 16; ++t) kl[t] = (0x007FFFFFull << 32) | (unsigned)(15 - t);
    float vminf = __int_as_float(0xFF800000);  // -inf
    int cnt = 0;
    ull* mycol = &sbuf[0][tid];
    unsigned sbase = (unsigned)__cvta_generic_to_shared(mycol);

    for (int tt = 0; tt < CHUNK_N / TILE_C; ++tt) {
        int c0 = chunk * CHUNK_N + tt * TILE_C;
        __syncthreads();
        for (int i = tid; i < TPAIR; i += 128) {
            int j = c0 + 2 * i;
            float2 vx = *(const float2*)&pb[j];
            float2 vy = *(const float2*)&pb[Nn + j];
            float2 vz = *(const float2*)&pb[2 * Nn + j];
            float2 vs = *(const float2*)&g_sq[b * Nn + j];
            tx2[i] = pack2f(vx.x, vx.y);
            ty2[i] = pack2f(vy.x, vy.y);
            tz2[i] = pack2f(vz.x, vz.y);
            tns2[i] = pack2f(-vs.x, -vs.y);
        }
        __syncthreads();
        for (int jh = 0; jh < TPAIR; jh += 2) {
            ulonglong2 X = *(const ulonglong2*)&tx2[jh];
            ulonglong2 Y = *(const ulonglong2*)&ty2[jh];
            ulonglong2 Z = *(const ulonglong2*)&tz2[jh];
            ulonglong2 S = *(const ulonglong2*)&tns2[jh];
            ull t01 = fma2(qz2, Z.x, fma2(qy2, Y.x, mul2(qx2, X.x)));
            ull t23 = fma2(qz2, Z.y, fma2(qy2, Y.y, mul2(qx2, X.y)));
            ull d01 = add2(fma2(two2, t01, nqs2), S.x);
            ull d23 = add2(fma2(two2, t23, nqs2), S.y);
            float d0, d1, d2, d3;
            unpack2(d01, d0, d1);
            unpack2(d23, d2, d3);
            // branch-free predicated appends (raw entries; transform in flush)
            unsigned nj = ~(unsigned)(c0 + 2 * jh);
            append1(sbase, cnt, d0, vminf, nj);
            append1(sbase, cnt, d1, vminf, nj - 1);
            append1(sbase, cnt, d2, vminf, nj - 2);
            append1(sbase, cnt, d3, vminf, nj - 3);
            if (__any_sync(0xFFFFFFFFu, cnt > 12)) {
                flush_merge(kl, mycol, cnt);
                cnt = 0;
                vminf = key_val(kl[15]);
            }
        }
    }
    if (__any_sync(0xFFFFFFFFu, cnt > 0)) flush_merge(kl, mycol, cnt);

    ull* outp = g_pk + (((size_t)b * Nn + n) * S_CHUNK + chunk) * 16;
#pragma unroll
    for (int t = 0; t < 16; ++t) outp[t] = kl[t];
}

// ---------------- KNN merge: 4-way bitonic merge of sorted chunk lists ------
__global__ void knn_merge() {
    int q = blockIdx.x * 128 + threadIdx.x;  // 0 .. Bb*Nn-1
    const ull* base = g_pk + (size_t)q * (S_CHUNK * 16);
    ull m01[16], t[16];
#pragma unroll
    for (int i = 0; i < 16; ++i) m01[i] = base[i];
#pragma unroll
    for (int i = 0; i < 16; ++i) t[i] = base[16 + i];
    merge16(m01, t);
    ull m23[16];
#pragma unroll
    for (int i = 0; i < 16; ++i) m23[i] = base[32 + i];
#pragma unroll
    for (int i = 0; i < 16; ++i) t[i] = base[48 + i];
    merge16(m23, t);
    merge16(m01, m23);
    int* op = g_idx + (size_t)q * 16;
#pragma unroll
    for (int i = 0; i < 16; ++i) op[i] = (int)(~(unsigned)m01[i]);
}

// ---------------- fused gather + spectral GEMM + BN partials ----------------
// R12-proven form: 64p x 64d tile, 256 threads, 4p x 4d micro-tile,
// pack-in-loop FMA2, two barriers per stage, 2x16KB static smem, W via LDS.128.
// 17 stages: k=0..15 neighbors w/ filter_k; k=16 self w/ -sum_k filter.
__global__ void gconv_kernel(const float* __restrict__ filt, float* __restrict__ out) {
    __shared__ __align__(16) float Esm[64 * 64];  // [c][p]
    __shared__ __align__(16) float Wsm[64 * 64];  // [c][d]
    int b = blockIdx.y;
    int n0 = blockIdx.x * 64;
    int tid = threadIdx.x;
    int tx = tid & 15, ty = tid >> 4;         // d-quad, p-quad
    int p = tid & 63, cg = tid >> 6;          // staging roles

    ull acc2[4][2];
#pragma unroll
    for (int i = 0; i < 4; ++i) { acc2[i][0] = 0ull; acc2[i][1] = 0ull; }

    const float* xTb = g_xT + (size_t)b * Nn * Cc;

    for (int kk = 0; kk <= Kk; ++kk) {
        const float* Wsrc = (kk < Kk) ? (filt + kk * Cc * Dd) : g_WsumNeg;
#pragma unroll
        for (int i = 0; i < 4; ++i)
            ((float4*)Wsm)[tid + 256 * i] = ((const float4*)Wsrc)[tid + 256 * i];
        int m = (kk < Kk) ? g_idx[((size_t)b * Nn + n0 + p) * Kk + kk] : (n0 + p);
        const float* row = xTb + (size_t)m * Cc + cg * 16;
#pragma unroll
        for (int i = 0; i < 4; ++i) {
            float4 vv = ((const float4*)row)[i];
            int c = cg * 16 + i * 4;
            Esm[(c + 0) * 64 + p] = vv.x;
            Esm[(c + 1) * 64 + p] = vv.y;
            Esm[(c + 2) * 64 + p] = vv.z;
            Esm[(c + 3) * 64 + p] = vv.w;
        }
        __syncthreads();
#pragma unroll 8
        for (int c = 0; c < 64; ++c) {
            float4 e = *(const float4*)&Esm[c * 64 + ty * 4];
            ulonglong2 w = *(const ulonglong2*)&Wsm[c * 64 + tx * 4];  // one LDS.128
            ull ex = pack2(e.x), ey = pack2(e.y), ez = pack2(e.z), ew = pack2(e.w);
            FMA2(acc2[0][0], ex, w.x); FMA2(acc2[0][1], ex, w.y);
            FMA2(acc2[1][0], ey, w.x); FMA2(acc2[1][1], ey, w.y);
            FMA2(acc2[2][0], ez, w.x); FMA2(acc2[2][1], ez, w.y);
            FMA2(acc2[3][0], ew, w.x); FMA2(acc2[3][1], ew, w.y);
        }
        __syncthreads();
    }

    float acc[4][4];
#pragma unroll
    for (int i = 0; i < 4; ++i) {
        unpack2(acc2[i][0], acc[i][0], acc[i][1]);
        unpack2(acc2[i][1], acc[i][2], acc[i][3]);
    }

    float psum[4], psq[4];
#pragma unroll
    for (int j = 0; j < 4; ++j) {
        psum[j] = acc[0][j] + acc[1][j] + acc[2][j] + acc[3][j];
        psq[j] = acc[0][j] * acc[0][j] + acc[1][j] * acc[1][j] +
                 acc[2][j] * acc[2][j] + acc[3][j] * acc[3][j];
    }
#pragma unroll
    for (int i = 0; i < 4; ++i)
#pragma unroll
        for (int j = 0; j < 4; ++j)
            Esm[(tx * 4 + j) * 64 + (ty * 4 + i)] = acc[i][j];
#pragma unroll
    for (int j = 0; j < 4; ++j) Wsm[ty * 64 + tx * 4 + j] = psum[j];
    __syncthreads();

    {
        int d = tid >> 2, seg = tid & 3;
        float4* orow = (float4*)(out + (size_t)b * Dd * Nn + (size_t)d * Nn + n0);
        const float4* trow = (const float4*)&Esm[d * 64];
#pragma unroll
        for (int qq = 0; qq < 4; ++qq) orow[seg * 4 + qq] = trow[seg * 4 + qq];
    }
    int blk = b * gridDim.x + blockIdx.x;
    if (tid < 64) {
        float s = 0.f;
#pragma unroll
        for (int t = 0; t < 16; ++t) s += Wsm[t * 64 + tid];
        g_partial[blk * 128 + tid] = s;
    }
    __syncthreads();
#pragma unroll
    for (int j = 0; j < 4; ++j) Wsm[ty * 64 + tx * 4 + j] = psq[j];
    __syncthreads();
    if (tid < 64) {
        float s = 0.f;
#pragma unroll
        for (int t = 0; t < 16; ++t) s += Wsm[t * 64 + tid];
        g_partial[blk * 128 + 64 + tid] = s;
    }
}

// ---------------- finalize BN stats (deterministic) -------------------------
__global__ void finalize_kernel(const float* __restrict__ gamma, const float* __restrict__ beta) {
    int d = threadIdx.x;  // 64 threads
    float s = 0.f, s2 = 0.f;
    const int nblk = Bb * Nn / 64;
#pragma unroll 8
    for (int blk = 0; blk < nblk; ++blk) {
        s += g_partial[blk * 128 + d];
        s2 += g_partial[blk * 128 + 64 + d];
    }
    const float inv = 1.0f / (float)(Bb * Nn);
    float mean = s * inv;
    float var = s2 * inv - mean * mean;
    float sc = gamma[d] * rsqrtf(var + 1e-5f);
    g_scale[d] = sc;
    g_shift[d] = beta[d] - mean * sc;
}

// ---------------- apply BN in place on d_out --------------------------------
__global__ void bn_apply(float* __restrict__ out) {
    int i = blockIdx.x * 256 + threadIdx.x;
    float4 v = ((float4*)out)[i];
    int d = (i >> 11) & 63;
    float sc = g_scale[d], sh = g_shift[d];
    v.x = fmaf(v.x, sc, sh);
    v.y = fmaf(v.y, sc, sh);
    v.z = fmaf(v.z, sc, sh);
    v.w = fmaf(v.w, sc, sh);
    ((float4*)out)[i] = v;
}

// ---------------- launch ----------------------------------------------------
extern "C" void kernel_launch(void* const* d_in, const int* in_sizes, int n_in,
                              void* d_out, int out_size) {
    const float* x = (const float*)d_in[0];
    const float* pos = (const float*)d_in[1];
    const float* filt = (const float*)d_in[2];
    const float* gamma = (const float*)d_in[3];
    const float* beta = (const float*)d_in[4];
    float* out = (float*)d_out;

    prep_sq<<<dim3(Nn / 256, Bb), 256>>>(pos);
    prep_xT<<<dim3(Nn / 32, Cc / 32, Bb), dim3(32, 8)>>>(x);
    prep_wsum<<<(Cc * Dd) / 256, 256>>>(filt);
    knn_partial<<<dim3(Nn / 128, S_CHUNK, Bb), 128>>>(pos);
    knn_merge<<<(Bb * Nn) / 128, 128>>>();
    gconv_kernel<<<dim3(Nn / 64, Bb), 256>>>(filt, out);
    finalize_kernel<<<1, 64>>>(gamma, beta);
    bn_apply<<<(Bb * Dd * Nn / 4) / 256, 256>>>(out);
}

// round 17
// speedup vs baseline: 1.0191x; 1.0191x over previous
#include <cuda_runtime.h>

#define Bb 4
#define Cc 64
#define Nn 8192
#define Kk 16
#define Dd 64
#define S_CHUNK 4
#define CHUNK_N (Nn / S_CHUNK)
#define TILE_C 1024
#define TPAIR (TILE_C / 2)

typedef unsigned long long ull;

// ---------------- scratch (static __device__, no allocations) ----------------
__device__ __align__(16) float g_xT[Bb * Nn * Cc];       // x transposed: (B, N, C)
__device__ float g_sq[Bb * Nn];                          // squared norms of pos
__device__ int   g_idx[Bb * Nn * Kk];                    // knn indices
__device__ __align__(16) ull g_pk[(size_t)Bb * Nn * S_CHUNK * 16]; // partial sorted keys
__device__ __align__(16) float g_WsumNeg[Cc * Dd];       // -sum_k W[k,c,d]
__device__ float g_partial[(Bb * Nn / 64) * 2 * Dd];     // per-block BN partials (sum, sumsq)
__device__ float g_scale[Dd], g_shift[Dd];

// ---------------- f32x2 helpers ---------------------------------------------
#define FMA2(d, a, b) asm("fma.rn.f32x2 %0, %1, %2, %0;" : "+l"(d) : "l"(a), "l"(b))
__device__ __forceinline__ ull mul2(ull a, ull b) {
    ull r; asm("mul.rn.f32x2 %0, %1, %2;" : "=l"(r) : "l"(a), "l"(b)); return r;
}
__device__ __forceinline__ ull fma2(ull a, ull b, ull c) {
    ull r; asm("fma.rn.f32x2 %0, %1, %2, %3;" : "=l"(r) : "l"(a), "l"(b), "l"(c)); return r;
}
__device__ __forceinline__ ull add2(ull a, ull b) {
    ull r; asm("add.rn.f32x2 %0, %1, %2;" : "=l"(r) : "l"(a), "l"(b)); return r;
}
__device__ __forceinline__ ull pack2(float x) {
    ull r; asm("mov.b64 %0, {%1, %1};" : "=l"(r) : "r"(__float_as_uint(x))); return r;
}
__device__ __forceinline__ ull pack2f(float a, float b) {
    ull r; asm("mov.b64 %0, {%1, %2};" : "=l"(r) : "r"(__float_as_uint(a)), "r"(__float_as_uint(b))); return r;
}
__device__ __forceinline__ void unpack2(ull v, float& lo, float& hi) {
    unsigned a, b;
    asm("mov.b64 {%0, %1}, %2;" : "=r"(a), "=r"(b) : "l"(v));
    lo = __uint_as_float(a); hi = __uint_as_float(b);
}

// ---------------- prep: squared norms of pos --------------------------------
// Match XLA reduce lowering exactly: ((x*x + y*y) + z*z), no fma contraction.
__global__ void prep_sq(const float* __restrict__ pos) {
    int b = blockIdx.y;
    int n = blockIdx.x * 256 + threadIdx.x;
    const float* pb = pos + b * 3 * Nn;
    float x = pb[n], y = pb[Nn + n], z = pb[2 * Nn + n];
    float s = __fadd_rn(__fadd_rn(__fmul_rn(x, x), __fmul_rn(y, y)), __fmul_rn(z, z));
    g_sq[b * Nn + n] = s;
}

// ---------------- prep: transpose x (B,C,N) -> xT (B,N,C) -------------------
__global__ void prep_xT(const float* __restrict__ x) {
    __shared__ float t[32][33];
    int b = blockIdx.z;
    int n0 = blockIdx.x * 32, c0 = blockIdx.y * 32;
    int tx = threadIdx.x, ty = threadIdx.y;
#pragma unroll
    for (int i = 0; i < 4; ++i)
        t[ty + 8 * i][tx] = x[(size_t)b * Cc * Nn + (size_t)(c0 + ty + 8 * i) * Nn + n0 + tx];
    __syncthreads();
#pragma unroll
    for (int i = 0; i < 4; ++i)
        g_xT[(size_t)b * Nn * Cc + (size_t)(n0 + ty + 8 * i) * Cc + c0 + tx] = t[tx][ty + 8 * i];
}

// ---------------- prep: negated filter k-sum --------------------------------
__global__ void prep_wsum(const float* __restrict__ filt) {
    int i = blockIdx.x * 256 + threadIdx.x;  // 0..4095 = c*64+d
    float s = 0.f;
#pragma unroll
    for (int k = 0; k < Kk; ++k) s += filt[k * Cc * Dd + i];
    g_WsumNeg[i] = -s;
}

// ---------------- KNN keys ---------------------------------------------------
// Transformed key: (sortable(dn) << 32) | ~idx -> total order == top_k
// (value desc, idx asc). Keys are UNIQUE, so selection is a pure multiset
// top-16: any order-insensitive exact top-16 structure is bit-identical.
// Appends store RAW (d_bits<<32)|~idx; the sortable transform is applied in
// flush_merge (16 items per flush instead of per candidate).
__device__ __forceinline__ float key_val(ull k) {
    unsigned u = (unsigned)(k >> 32);
    unsigned tb = (u & 0x80000000u) ? (u ^ 0x80000000u) : ~u;
    return __int_as_float((int)tb);
}

// Branch-free predicated append: no BSSY/BSYNC region.
__device__ __forceinline__ void append1(unsigned sbase, int& cnt, float d, float vminf, unsigned nj) {
    unsigned hi = __float_as_uint(d);
    unsigned addr = sbase + (unsigned)cnt * 1024u;
    asm volatile(
        "{ .reg .pred p; .reg .b64 v;\n\t"
        "setp.ge.f32 p, %0, %1;\n\t"
        "mov.b64 v, {%3, %4};\n\t"
        "@p st.shared.b64 [%2], v; }"
        :: "f"(d), "f"(vminf), "r"(addr), "r"(nj), "r"(hi));
    cnt += (d >= vminf);
}

// Merge two descending sorted 16-lists -> top-16 descending (pair-max + bitonic).
__device__ __forceinline__ void merge16(ull (&kl)[16], const ull (&other)[16]) {
    ull m[16];
#pragma unroll
    for (int i = 0; i < 16; ++i) { ull a = kl[i], c = other[15 - i]; m[i] = a > c ? a : c; }
#pragma unroll
    for (int j = 8; j > 0; j >>= 1) {
#pragma unroll
        for (int i = 0; i < 16; ++i) {
            int l = i ^ j;
            if (l > i) {
                ull a = m[i], c = m[l];
                bool sw = a < c;
                m[i] = sw ? c : a;
                m[l] = sw ? a : c;
            }
        }
    }
#pragma unroll
    for (int i = 0; i < 16; ++i) kl[i] = m[i];
}

// Batched exact top-16 update: transform raw entries to sortable keys,
// bitonic-sort the buffer (desc), then merge16. kl stays sorted descending.
__device__ __forceinline__ void flush_merge(ull (&kl)[16], const ull* col, int cnt) {
    ull buf[16];
#pragma unroll
    for (int m = 0; m < 16; ++m) {
        ull raw = (m < cnt) ? col[m * 128] : 0ull;
        int bi = (int)(unsigned)(raw >> 32);
        unsigned u = (unsigned)(bi ^ ((bi >> 31) | 0x80000000));
        buf[m] = (m < cnt) ? (((ull)u << 32) | (unsigned)raw) : 0ull;
    }
    // bitonic sort, descending
#pragma unroll
    for (int k = 2; k <= 16; k <<= 1) {
#pragma unroll
        for (int j = k >> 1; j > 0; j >>= 1) {
#pragma unroll
            for (int i = 0; i < 16; ++i) {
                int l = i ^ j;
                if (l > i) {
                    bool desc = ((i & k) == 0);
                    ull a = buf[i], c = buf[l];
                    bool sw = desc ? (a < c) : (a > c);
                    buf[i] = sw ? c : a;
                    buf[l] = sw ? a : c;
                }
            }
        }
    }
    merge16(kl, buf);
}

// ---------------- KNN partial: top-16 within a 2048-candidate chunk ---------
// 1024-candidate tiles (16KB) -> 33KB smem/block -> 5 blocks/SM (measured
// optimum: 4 blocks (R13) and forced-6 (R15) are both slower).
// Packed f32x2 arithmetic; per-lane rounding identical to scalar chain
// (2*inner is exact, so fma(2,t,-qs) == add(mul(2,t),-qs) bitwise).
__global__ void __launch_bounds__(128, 5) knn_partial(const float* __restrict__ pos) {
    __shared__ __align__(16) ull tx2[TPAIR], ty2[TPAIR], tz2[TPAIR], tns2[TPAIR];
    __shared__ ull sbuf[16][128];
    int b = blockIdx.z;
    int chunk = blockIdx.y;
    int tid = threadIdx.x;
    int n = blockIdx.x * 128 + tid;
    const float* pb = pos + b * 3 * Nn;
    float qxs = pb[n], qys = pb[Nn + n], qzs = pb[2 * Nn + n];
    float qss = g_sq[b * Nn + n];
    ull qx2 = pack2(qxs), qy2 = pack2(qys), qz2 = pack2(qzs);
    ull nqs2 = pack2(-qss), two2 = pack2(2.0f);

    // sentinel keys: descending, distinct; kl[15] decodes below any real key
    ull kl[16];
#pragma unroll
    for (int t = 0; t < 16; ++t) kl[t] = (0x007FFFFFull << 32) | (unsigned)(15 - t);
    float vminf = __int_as_float(0xFF800000);  // -inf
    int cnt = 0;
    ull* mycol = &sbuf[0][tid];
    unsigned sbase = (unsigned)__cvta_generic_to_shared(mycol);

    for (int tt = 0; tt < CHUNK_N / TILE_C; ++tt) {
        int c0 = chunk * CHUNK_N + tt * TILE_C;
        __syncthreads();
        for (int i = tid; i < TPAIR; i += 128) {
            int j = c0 + 2 * i;
            float2 vx = *(const float2*)&pb[j];
            float2 vy = *(const float2*)&pb[Nn + j];
            float2 vz = *(const float2*)&pb[2 * Nn + j];
            float2 vs = *(const float2*)&g_sq[b * Nn + j];
            tx2[i] = pack2f(vx.x, vx.y);
            ty2[i] = pack2f(vy.x, vy.y);
            tz2[i] = pack2f(vz.x, vz.y);
            tns2[i] = pack2f(-vs.x, -vs.y);
        }
        __syncthreads();
        for (int jh = 0; jh < TPAIR; jh += 2) {
            ulonglong2 X = *(const ulonglong2*)&tx2[jh];
            ulonglong2 Y = *(const ulonglong2*)&ty2[jh];
            ulonglong2 Z = *(const ulonglong2*)&tz2[jh];
            ulonglong2 S = *(const ulonglong2*)&tns2[jh];
            ull t01 = fma2(qz2, Z.x, fma2(qy2, Y.x, mul2(qx2, X.x)));
            ull t23 = fma2(qz2, Z.y, fma2(qy2, Y.y, mul2(qx2, X.y)));
            ull d01 = add2(fma2(two2, t01, nqs2), S.x);
            ull d23 = add2(fma2(two2, t23, nqs2), S.y);
            float d0, d1, d2, d3;
            unpack2(d01, d0, d1);
            unpack2(d23, d2, d3);
            // branch-free predicated appends (raw entries; transform in flush)
            unsigned nj = ~(unsigned)(c0 + 2 * jh);
            append1(sbase, cnt, d0, vminf, nj);
            append1(sbase, cnt, d1, vminf, nj - 1);
            append1(sbase, cnt, d2, vminf, nj - 2);
            append1(sbase, cnt, d3, vminf, nj - 3);
            if (__any_sync(0xFFFFFFFFu, cnt > 12)) {
                flush_merge(kl, mycol, cnt);
                cnt = 0;
                vminf = key_val(kl[15]);
            }
        }
    }
    if (__any_sync(0xFFFFFFFFu, cnt > 0)) flush_merge(kl, mycol, cnt);

    ull* outp = g_pk + (((size_t)b * Nn + n) * S_CHUNK + chunk) * 16;
#pragma unroll
    for (int t = 0; t < 16; ++t) outp[t] = kl[t];
}

// ---------------- KNN merge: 4-way bitonic merge of sorted chunk lists ------
__global__ void knn_merge() {
    int q = blockIdx.x * 128 + threadIdx.x;  // 0 .. Bb*Nn-1
    const ull* base = g_pk + (size_t)q * (S_CHUNK * 16);
    ull m01[16], t[16];
#pragma unroll
    for (int i = 0; i < 16; ++i) m01[i] = base[i];
#pragma unroll
    for (int i = 0; i < 16; ++i) t[i] = base[16 + i];
    merge16(m01, t);
    ull m23[16];
#pragma unroll
    for (int i = 0; i < 16; ++i) m23[i] = base[32 + i];
#pragma unroll
    for (int i = 0; i < 16; ++i) t[i] = base[48 + i];
    merge16(m23, t);
    merge16(m01, m23);
    int* op = g_idx + (size_t)q * 16;
#pragma unroll
    for (int i = 0; i < 16; ++i) op[i] = (int)(~(unsigned)m01[i]);
}

// ---------------- fused gather + spectral GEMM + BN partials ----------------
// R12-proven form: 64p x 64d tile, 256 threads, 4p x 4d micro-tile,
// pack-in-loop FMA2, two barriers per stage, 2x16KB static smem, W via LDS.128.
// 17 stages: k=0..15 neighbors w/ filter_k; k=16 self w/ -sum_k filter.
__global__ void gconv_kernel(const float* __restrict__ filt, float* __restrict__ out) {
    __shared__ __align__(16) float Esm[64 * 64];  // [c][p]
    __shared__ __align__(16) float Wsm[64 * 64];  // [c][d]
    int b = blockIdx.y;
    int n0 = blockIdx.x * 64;
    int tid = threadIdx.x;
    int tx = tid & 15, ty = tid >> 4;         // d-quad, p-quad
    int p = tid & 63, cg = tid >> 6;          // staging roles

    ull acc2[4][2];
#pragma unroll
    for (int i = 0; i < 4; ++i) { acc2[i][0] = 0ull; acc2[i][1] = 0ull; }

    const float* xTb = g_xT + (size_t)b * Nn * Cc;

    for (int kk = 0; kk <= Kk; ++kk) {
        const float* Wsrc = (kk < Kk) ? (filt + kk * Cc * Dd) : g_WsumNeg;
#pragma unroll
        for (int i = 0; i < 4; ++i)
            ((float4*)Wsm)[tid + 256 * i] = ((const float4*)Wsrc)[tid + 256 * i];
        int m = (kk < Kk) ? g_idx[((size_t)b * Nn + n0 + p) * Kk + kk] : (n0 + p);
        const float* row = xTb + (size_t)m * Cc + cg * 16;
#pragma unroll
        for (int i = 0; i < 4; ++i) {
            float4 vv = ((const float4*)row)[i];
            int c = cg * 16 + i * 4;
            Esm[(c + 0) * 64 + p] = vv.x;
            Esm[(c + 1) * 64 + p] = vv.y;
            Esm[(c + 2) * 64 + p] = vv.z;
            Esm[(c + 3) * 64 + p] = vv.w;
        }
        __syncthreads();
#pragma unroll 8
        for (int c = 0; c < 64; ++c) {
            float4 e = *(const float4*)&Esm[c * 64 + ty * 4];
            ulonglong2 w = *(const ulonglong2*)&Wsm[c * 64 + tx * 4];  // one LDS.128
            ull ex = pack2(e.x), ey = pack2(e.y), ez = pack2(e.z), ew = pack2(e.w);
            FMA2(acc2[0][0], ex, w.x); FMA2(acc2[0][1], ex, w.y);
            FMA2(acc2[1][0], ey, w.x); FMA2(acc2[1][1], ey, w.y);
            FMA2(acc2[2][0], ez, w.x); FMA2(acc2[2][1], ez, w.y);
            FMA2(acc2[3][0], ew, w.x); FMA2(acc2[3][1], ew, w.y);
        }
        __syncthreads();
    }

    float acc[4][4];
#pragma unroll
    for (int i = 0; i < 4; ++i) {
        unpack2(acc2[i][0], acc[i][0], acc[i][1]);
        unpack2(acc2[i][1], acc[i][2], acc[i][3]);
    }

    float psum[4], psq[4];
#pragma unroll
    for (int j = 0; j < 4; ++j) {
        psum[j] = acc[0][j] + acc[1][j] + acc[2][j] + acc[3][j];
        psq[j] = acc[0][j] * acc[0][j] + acc[1][j] * acc[1][j] +
                 acc[2][j] * acc[2][j] + acc[3][j] * acc[3][j];
    }
#pragma unroll
    for (int i = 0; i < 4; ++i)
#pragma unroll
        for (int j = 0; j < 4; ++j)
            Esm[(tx * 4 + j) * 64 + (ty * 4 + i)] = acc[i][j];
#pragma unroll
    for (int j = 0; j < 4; ++j) Wsm[ty * 64 + tx * 4 + j] = psum[j];
    __syncthreads();

    {
        int d = tid >> 2, seg = tid & 3;
        float4* orow = (float4*)(out + (size_t)b * Dd * Nn + (size_t)d * Nn + n0);
        const float4* trow = (const float4*)&Esm[d * 64];
#pragma unroll
        for (int qq = 0; qq < 4; ++qq) orow[seg * 4 + qq] = trow[seg * 4 + qq];
    }
    int blk = b * gridDim.x + blockIdx.x;
    if (tid < 64) {
        float s = 0.f;
#pragma unroll
        for (int t = 0; t < 16; ++t) s += Wsm[t * 64 + tid];
        g_partial[blk * 128 + tid] = s;
    }
    __syncthreads();
#pragma unroll
    for (int j = 0; j < 4; ++j) Wsm[ty * 64 + tx * 4 + j] = psq[j];
    __syncthreads();
    if (tid < 64) {
        float s = 0.f;
#pragma unroll
        for (int t = 0; t < 16; ++t) s += Wsm[t * 64 + tid];
        g_partial[blk * 128 + 64 + tid] = s;
    }
}

// ---------------- finalize BN stats (deterministic) -------------------------
__global__ void finalize_kernel(const float* __restrict__ gamma, const float* __restrict__ beta) {
    int d = threadIdx.x;  // 64 threads
    float s = 0.f, s2 = 0.f;
    const int nblk = Bb * Nn / 64;
#pragma unroll 8
    for (int blk = 0; blk < nblk; ++blk) {
        s += g_partial[blk * 128 + d];
        s2 += g_partial[blk * 128 + 64 + d];
    }
    const float inv = 1.0f / (float)(Bb * Nn);
    float mean = s * inv;
    float var = s2 * inv - mean * mean;
    float sc = gamma[d] * rsqrtf(var + 1e-5f);
    g_scale[d] = sc;
    g_shift[d] = beta[d] - mean * sc;
}

// ---------------- apply BN in place on d_out --------------------------------
__global__ void bn_apply(float* __restrict__ out) {
    int i = blockIdx.x * 256 + threadIdx.x;
    float4 v = ((float4*)out)[i];
    int d = (i >> 11) & 63;
    float sc = g_scale[d], sh = g_shift[d];
    v.x = fmaf(v.x, sc, sh);
    v.y = fmaf(v.y, sc, sh);
    v.z = fmaf(v.z, sc, sh);
    v.w = fmaf(v.w, sc, sh);
    ((float4*)out)[i] = v;
}

// ---------------- launch ----------------------------------------------------
extern "C" void kernel_launch(void* const* d_in, const int* in_sizes, int n_in,
                              void* d_out, int out_size) {
    const float* x = (const float*)d_in[0];
    const float* pos = (const float*)d_in[1];
    const float* filt = (const float*)d_in[2];
    const float* gamma = (const float*)d_in[3];
    const float* beta = (const float*)d_in[4];
    float* out = (float*)d_out;

    prep_sq<<<dim3(Nn / 256, Bb), 256>>>(pos);
    prep_xT<<<dim3(Nn / 32, Cc / 32, Bb), dim3(32, 8)>>>(x);
    prep_wsum<<<(Cc * Dd) / 256, 256>>>(filt);
    knn_partial<<<dim3(Nn / 128, S_CHUNK, Bb), 128>>>(pos);
    knn_merge<<<(Bb * Nn) / 128, 128>>>();
    gconv_kernel<<<dim3(Nn / 64, Bb), 256>>>(filt, out);
    finalize_kernel<<<1, 64>>>(gamma, beta);
    bn_apply<<<(Bb * Dd * Nn / 4) / 256, 256>>>(out);
}